// round 3
// baseline (speedup 1.0000x reference)
#include <cuda_runtime.h>
#include <cuda_bf16.h>
#include <math.h>

#define L_ 4
#define H_ 8
#define D_ 512
#define HD_ 64
#define F_ 2048
#define V_ 32000
#define B_ 2
#define S_ 2048
#define M_ (B_ * S_)   // 4096 tokens
#define QKV_ (3 * D_)  // 1536

// ---------------- scratch (no allocations allowed) ----------------
__device__ float g_x[M_ * D_];
__device__ float g_qkv[M_ * QKV_];   // fused q|k|v, row stride 1536
__device__ float g_o[M_ * D_];       // attn out / ffn2 tmp
__device__ float g_h[M_ * F_];       // ffn hidden / proj tmp
__device__ float g_w[D_ * QKV_];     // repacked [D][3D] qkv weight for current layer

// ---------------- embedding + sinusoidal PE ----------------
__global__ void embed_kernel(const int* __restrict__ tokens,
                             const float* __restrict__ emb,
                             float* __restrict__ x) {
    int i = blockIdx.x * blockDim.x + threadIdx.x;
    if (i >= M_ * D_) return;
    int m = i / D_, d = i % D_;
    int s = m % S_;
    int tok = tokens[m];
    float expo = (float)(d & ~1) * (-logf(10000.0f) / (float)D_);
    float div = expf(expo);
    float ang = (float)s * div;
    float pe = (d & 1) ? cosf(ang) : sinf(ang);
    x[i] = emb[tok * D_ + d] + pe;
}

// ---------------- repack QKV weights [H][D][HD] -> [D][3D] (q|k|v) ----------------
__global__ void repack_qkv(const float* __restrict__ Wq,
                           const float* __restrict__ Wk,
                           const float* __restrict__ Wv,
                           float* __restrict__ w) {
    int i = blockIdx.x * blockDim.x + threadIdx.x;
    if (i >= D_ * D_) return;
    int d = i / D_, n = i % D_;
    int h = n / HD_, e = n % HD_;
    int src = h * D_ * HD_ + d * HD_ + e;
    w[(size_t)d * QKV_ + n]            = Wq[src];
    w[(size_t)d * QKV_ + D_ + n]       = Wk[src];
    w[(size_t)d * QKV_ + 2 * D_ + n]   = Wv[src];
}

// ---------------- SGEMM: C[M,N] = A[M,K] @ B + bias (+relu) ----------------
// TRANSB=false: B is [K,N] row-major.  TRANSB=true: B is [N,K] row-major.
// Requires M%128==0, N%128==0, K%8==0.
template <bool TRANSB, bool RELU>
__global__ __launch_bounds__(256)
void sgemm(const float* __restrict__ A, const float* __restrict__ B,
           const float* __restrict__ bias, float* __restrict__ C,
           int M, int N, int K) {
    __shared__ float As[8][128];
    __shared__ float Bs[8][128];
    int tid = threadIdx.x;
    int bm = blockIdx.y * 128, bn = blockIdx.x * 128;
    int arow = tid >> 1, acol = (tid & 1) * 4;
    int tx = tid & 15, ty = tid >> 4;

    float acc[8][8];
#pragma unroll
    for (int i = 0; i < 8; i++)
#pragma unroll
        for (int j = 0; j < 8; j++) acc[i][j] = 0.0f;

    for (int k0 = 0; k0 < K; k0 += 8) {
        float4 av = *(const float4*)&A[(size_t)(bm + arow) * K + k0 + acol];
        As[acol + 0][arow] = av.x;
        As[acol + 1][arow] = av.y;
        As[acol + 2][arow] = av.z;
        As[acol + 3][arow] = av.w;
        if (!TRANSB) {
            int brow = tid >> 5, bcol = (tid & 31) * 4;
            float4 bv = *(const float4*)&B[(size_t)(k0 + brow) * N + bn + bcol];
            *(float4*)&Bs[brow][bcol] = bv;
        } else {
            int bni = tid >> 1, bk = (tid & 1) * 4;
            float4 bv = *(const float4*)&B[(size_t)(bn + bni) * K + k0 + bk];
            Bs[bk + 0][bni] = bv.x;
            Bs[bk + 1][bni] = bv.y;
            Bs[bk + 2][bni] = bv.z;
            Bs[bk + 3][bni] = bv.w;
        }
        __syncthreads();
#pragma unroll
        for (int kk = 0; kk < 8; kk++) {
            float a[8], bb[8];
            *(float4*)&a[0] = *(float4*)&As[kk][ty * 8];
            *(float4*)&a[4] = *(float4*)&As[kk][ty * 8 + 4];
            *(float4*)&bb[0] = *(float4*)&Bs[kk][tx * 8];
            *(float4*)&bb[4] = *(float4*)&Bs[kk][tx * 8 + 4];
#pragma unroll
            for (int i = 0; i < 8; i++)
#pragma unroll
                for (int j = 0; j < 8; j++) acc[i][j] += a[i] * bb[j];
        }
        __syncthreads();
    }

#pragma unroll
    for (int i = 0; i < 8; i++) {
        int r = bm + ty * 8 + i;
#pragma unroll
        for (int j = 0; j < 8; j++) {
            int c = bn + tx * 8 + j;
            float vv = acc[i][j];
            if (bias) vv += bias[c];
            if (RELU) vv = fmaxf(vv, 0.0f);
            C[(size_t)r * N + c] = vv;
        }
    }
}

// ---------------- causal flash attention (fp32, thread-per-query) ----------------
// grid: (S/128, B*H), 128 threads. qkv is [M, 1536] (q|k|v), o is [M, 512].
__global__ __launch_bounds__(128)
void attn_kernel(const float* __restrict__ qkv, float* __restrict__ o) {
    __shared__ float Ks[64][64];
    __shared__ float Vs[64][64];
    int bh = blockIdx.y;
    int b = bh / H_, h = bh % H_;
    int sq = blockIdx.x * 128 + threadIdx.x;
    int row = b * S_ + sq;

    const float* q = qkv;
    const float* k = qkv + D_;
    const float* v = qkv + 2 * D_;

    float qr[64];
#pragma unroll
    for (int d = 0; d < 64; d++) qr[d] = q[(size_t)row * QKV_ + h * HD_ + d];

    float mx = -1e30f, l = 0.0f;
    float acc[64];
#pragma unroll
    for (int d = 0; d < 64; d++) acc[d] = 0.0f;

    const float scale = 0.125f;  // HD^-0.5
    int ntiles = blockIdx.x * 2 + 2;  // covers keys 0 .. blockIdx.x*128+127

    for (int t = 0; t < ntiles; t++) {
        for (int i = threadIdx.x; i < 64 * 16; i += 128) {
            int j = i >> 4, d4 = (i & 15) * 4;
            size_t krow = (size_t)(b * S_ + t * 64 + j) * QKV_ + h * HD_ + d4;
            *(float4*)&Ks[j][d4] = *(const float4*)&k[krow];
            *(float4*)&Vs[j][d4] = *(const float4*)&v[krow];
        }
        __syncthreads();
        int jmax = sq - t * 64 + 1;
        if (jmax > 64) jmax = 64;
        for (int j = 0; j < jmax; j++) {
            float s = 0.0f;
            const float4* kp = (const float4*)&Ks[j][0];
#pragma unroll
            for (int d4 = 0; d4 < 16; d4++) {
                float4 kv = kp[d4];
                s += qr[d4 * 4 + 0] * kv.x + qr[d4 * 4 + 1] * kv.y +
                     qr[d4 * 4 + 2] * kv.z + qr[d4 * 4 + 3] * kv.w;
            }
            s *= scale;
            float mnew = fmaxf(mx, s);
            float corr = __expf(mx - mnew);
            float p = __expf(s - mnew);
            l = l * corr + p;
            const float4* vp = (const float4*)&Vs[j][0];
#pragma unroll
            for (int d4 = 0; d4 < 16; d4++) {
                float4 vv = vp[d4];
                acc[d4 * 4 + 0] = acc[d4 * 4 + 0] * corr + p * vv.x;
                acc[d4 * 4 + 1] = acc[d4 * 4 + 1] * corr + p * vv.y;
                acc[d4 * 4 + 2] = acc[d4 * 4 + 2] * corr + p * vv.z;
                acc[d4 * 4 + 3] = acc[d4 * 4 + 3] * corr + p * vv.w;
            }
            mx = mnew;
        }
        __syncthreads();
    }
    float inv = 1.0f / l;
#pragma unroll
    for (int d = 0; d < 64; d++)
        o[(size_t)row * D_ + h * HD_ + d] = acc[d] * inv;
}

// ---------------- residual + LayerNorm: x = LN(x + delta) * g + b ----------------
// delta may be null (plain LN). One block (128 threads) per row of D=512.
__global__ __launch_bounds__(128)
void ln_kernel(float* __restrict__ x, const float* __restrict__ delta,
               const float* __restrict__ gamma, const float* __restrict__ beta) {
    int row = blockIdx.x;
    int tid = threadIdx.x;
    __shared__ float red[128];

    float v[4];
    float s = 0.0f;
#pragma unroll
    for (int i = 0; i < 4; i++) {
        int d = i * 128 + tid;
        float t = x[(size_t)row * D_ + d];
        if (delta) t += delta[(size_t)row * D_ + d];
        v[i] = t;
        s += t;
    }
    red[tid] = s;
    __syncthreads();
    for (int off = 64; off > 0; off >>= 1) {
        if (tid < off) red[tid] += red[tid + off];
        __syncthreads();
    }
    float mean = red[0] * (1.0f / D_);
    __syncthreads();

    float s2 = 0.0f;
#pragma unroll
    for (int i = 0; i < 4; i++) {
        float dv = v[i] - mean;
        s2 += dv * dv;
    }
    red[tid] = s2;
    __syncthreads();
    for (int off = 64; off > 0; off >>= 1) {
        if (tid < off) red[tid] += red[tid + off];
        __syncthreads();
    }
    float var = red[0] * (1.0f / D_);
    float rstd = rsqrtf(var + 1e-5f);
#pragma unroll
    for (int i = 0; i < 4; i++) {
        int d = i * 128 + tid;
        x[(size_t)row * D_ + d] = (v[i] - mean) * rstd * gamma[d] + beta[d];
    }
}

// ---------------- launch ----------------
extern "C" void kernel_launch(void* const* d_in, const int* in_sizes, int n_in,
                              void* d_out, int out_size) {
    const int* tokens    = (const int*)d_in[0];
    const float* emb     = (const float*)d_in[1];
    const float* Wq      = (const float*)d_in[2];
    const float* Wk      = (const float*)d_in[3];
    const float* Wv      = (const float*)d_in[4];
    const float* Wo      = (const float*)d_in[5];
    const float* bo      = (const float*)d_in[6];
    const float* ln1_g   = (const float*)d_in[7];
    const float* ln1_b   = (const float*)d_in[8];
    const float* W1      = (const float*)d_in[9];
    const float* b1      = (const float*)d_in[10];
    const float* W2      = (const float*)d_in[11];
    const float* b2      = (const float*)d_in[12];
    const float* ln2_g   = (const float*)d_in[13];
    const float* ln2_b   = (const float*)d_in[14];
    const float* lnf_g   = (const float*)d_in[15];
    const float* lnf_b   = (const float*)d_in[16];
    const float* head_W  = (const float*)d_in[17];
    float* out = (float*)d_out;

    float *x, *qkv, *o, *h, *w;
    cudaGetSymbolAddress((void**)&x, g_x);
    cudaGetSymbolAddress((void**)&qkv, g_qkv);
    cudaGetSymbolAddress((void**)&o, g_o);
    cudaGetSymbolAddress((void**)&h, g_h);
    cudaGetSymbolAddress((void**)&w, g_w);

    embed_kernel<<<(M_ * D_ + 255) / 256, 256>>>(tokens, emb, x);

    dim3 gD(D_ / 128, M_ / 128);     // N=512
    dim3 gQKV(QKV_ / 128, M_ / 128); // N=1536
    dim3 gF(F_ / 128, M_ / 128);     // N=2048
    dim3 gV(V_ / 128, M_ / 128);     // N=32000
    dim3 gAttn(S_ / 128, B_ * H_);

    for (int l = 0; l < L_; l++) {
        const float* Wq_l = Wq + (size_t)l * H_ * D_ * HD_;
        const float* Wk_l = Wk + (size_t)l * H_ * D_ * HD_;
        const float* Wv_l = Wv + (size_t)l * H_ * D_ * HD_;
        const float* Wo_l = Wo + (size_t)l * D_ * D_;
        const float* bo_l = bo + (size_t)l * D_;
        const float* W1_l = W1 + (size_t)l * D_ * F_;
        const float* b1_l = b1 + (size_t)l * F_;
        const float* W2_l = W2 + (size_t)l * F_ * D_;
        const float* b2_l = b2 + (size_t)l * D_;

        repack_qkv<<<(D_ * D_ + 255) / 256, 256>>>(Wq_l, Wk_l, Wv_l, w);

        sgemm<false, false><<<gQKV, 256>>>(x, w, nullptr, qkv, M_, QKV_, D_);

        attn_kernel<<<gAttn, 128>>>(qkv, o);

        sgemm<false, false><<<gD, 256>>>(o, Wo_l, bo_l, h, M_, D_, D_);
        ln_kernel<<<M_, 128>>>(x, h, ln1_g + (size_t)l * D_, ln1_b + (size_t)l * D_);

        sgemm<false, true ><<<gF, 256>>>(x, W1_l, b1_l, h, M_, F_, D_);
        sgemm<false, false><<<gD, 256>>>(h, W2_l, b2_l, o, M_, D_, F_);
        ln_kernel<<<M_, 128>>>(x, o, ln2_g + (size_t)l * D_, ln2_b + (size_t)l * D_);
    }

    ln_kernel<<<M_, 128>>>(x, nullptr, lnf_g, lnf_b);
    sgemm<true, false><<<gV, 256>>>(x, head_W, nullptr, out, M_, V_, D_);
}

// round 5
// speedup vs baseline: 1.7163x; 1.7163x over previous
#include <cuda_runtime.h>
#include <cuda_bf16.h>
#include <math.h>
#include <stdint.h>

#define L_ 4
#define H_ 8
#define D_ 512
#define HD_ 64
#define F_ 2048
#define V_ 32000
#define B_ 2
#define S_ 2048
#define M_ (B_ * S_)   // 4096 tokens
#define QKV_ (3 * D_)  // 1536

// ---------------- scratch (no allocations allowed) ----------------
__device__ float g_x[M_ * D_];
__device__ float g_qkv[M_ * QKV_];
__device__ float g_o[M_ * D_];
__device__ float g_h[M_ * F_];
__device__ float g_wT[QKV_ * D_];    // [3D][D] K-major
__device__ float g_woT[D_ * D_];
__device__ float g_w1T[F_ * D_];
__device__ float g_w2T[D_ * F_];

// ==================== bf16 mma.sync GEMM ====================
// C[M,N] = A[M,K] @ Bt^T (+bias)(+relu), Bt is [N,K] row-major, fp32 in/out.
// Split-bf16: a = hi + lo (hi = truncated mantissa); C = Ah*Bh + Ah*Bl + Al*Bh.
// 128x128 CTA tile, 8 warps of 64x32, K-chunk 32, double-buffered smem.

#define KSTRIDE 40                      // 32 + 8 pad (bf16 elems per row)
#define BUF_B   (128 * KSTRIDE * 2)     // 10240 bytes per buffer
#define AHI_OFF 0
#define ALO_OFF (1 * BUF_B)
#define BHI_OFF (2 * BUF_B)
#define BLO_OFF (3 * BUF_B)
#define STG_B   (4 * BUF_B)             // 40960 per stage
#define SMEM_GEMM (2 * STG_B)           // 81920

__device__ __forceinline__ uint32_t smem_u32(const void* p) {
    uint32_t a;
    asm("{ .reg .u64 t; cvta.to.shared.u64 t, %1; cvt.u32.u64 %0, t; }"
        : "=r"(a) : "l"(p));
    return a;
}

#define LDSM4(r, addr)                                                          \
    asm volatile("ldmatrix.sync.aligned.m8n8.x4.shared.b16 {%0,%1,%2,%3}, [%4];" \
                 : "=r"((r)[0]), "=r"((r)[1]), "=r"((r)[2]), "=r"((r)[3])        \
                 : "r"(addr))
#define LDSM2(r, addr)                                                          \
    asm volatile("ldmatrix.sync.aligned.m8n8.x2.shared.b16 {%0,%1}, [%2];"       \
                 : "=r"((r)[0]), "=r"((r)[1]) : "r"(addr))
#define MMA(c, a, b)                                                            \
    asm volatile("mma.sync.aligned.m16n8k16.row.col.f32.bf16.bf16.f32 "          \
                 "{%0,%1,%2,%3}, {%4,%5,%6,%7}, {%8,%9}, {%0,%1,%2,%3};"         \
                 : "+f"((c)[0]), "+f"((c)[1]), "+f"((c)[2]), "+f"((c)[3])        \
                 : "r"((a)[0]), "r"((a)[1]), "r"((a)[2]), "r"((a)[3]),           \
                   "r"((b)[0]), "r"((b)[1]))

// split float4 into hi(truncated bf16) + lo(residual bf16), store both to smem
__device__ __forceinline__ void split_store(char* smb, int hiOff, int loOff,
                                            int elemOff, float4 v) {
    uint32_t u0 = __float_as_uint(v.x), u1 = __float_as_uint(v.y);
    uint32_t u2 = __float_as_uint(v.z), u3 = __float_as_uint(v.w);
    uint32_t h01 = __byte_perm(u0, u1, 0x7632);
    uint32_t h23 = __byte_perm(u2, u3, 0x7632);
    float l0 = v.x - __uint_as_float(u0 & 0xFFFF0000u);
    float l1 = v.y - __uint_as_float(u1 & 0xFFFF0000u);
    float l2 = v.z - __uint_as_float(u2 & 0xFFFF0000u);
    float l3 = v.w - __uint_as_float(u3 & 0xFFFF0000u);
    uint32_t lo01, lo23;
    asm("cvt.rn.bf16x2.f32 %0, %1, %2;" : "=r"(lo01) : "f"(l1), "f"(l0));
    asm("cvt.rn.bf16x2.f32 %0, %1, %2;" : "=r"(lo23) : "f"(l3), "f"(l2));
    *(uint2*)(smb + hiOff + elemOff * 2) = make_uint2(h01, h23);
    *(uint2*)(smb + loOff + elemOff * 2) = make_uint2(lo01, lo23);
}

__global__ __launch_bounds__(256)
void gemm_tc(const float* __restrict__ A, const float* __restrict__ Bt,
             const float* __restrict__ bias, float* __restrict__ C,
             int M, int N, int K, int relu) {
    extern __shared__ char sm[];
    uint32_t sb = smem_u32(sm);
    int tid = threadIdx.x, wid = tid >> 5, lane = tid & 31;
    int bm = blockIdx.y * 128, bn = blockIdx.x * 128;

    int warp_m = (wid & 1) * 64;
    int warp_n = (wid >> 1) * 32;

    // ldmatrix per-lane offsets (elems)
    uint32_t a_off = (uint32_t)(warp_m + (lane & 15)) * KSTRIDE + ((lane >> 4) << 3);
    uint32_t b_off = (uint32_t)(warp_n + (lane & 7)) * KSTRIDE + (((lane >> 3) & 1) << 3);

    // gmem load mapping: row = tid/2 (128 rows), half = tid&1 -> cols half*16 + i*4
    int lrow = tid >> 1, lhalf = tid & 1;
    int soff = lrow * KSTRIDE + lhalf * 16;  // smem elem offset base

    float acc[4][4][4];
#pragma unroll
    for (int mi = 0; mi < 4; mi++)
#pragma unroll
        for (int ni = 0; ni < 4; ni++)
#pragma unroll
            for (int f = 0; f < 4; f++) acc[mi][ni][f] = 0.0f;

    int nt = K >> 5;

    // prologue: fill stage 0
    {
        const float* Ar = &A[(size_t)(bm + lrow) * K + lhalf * 16];
        const float* Br = &Bt[(size_t)(bn + lrow) * K + lhalf * 16];
#pragma unroll
        for (int i = 0; i < 4; i++) {
            split_store(sm, AHI_OFF, ALO_OFF, soff + i * 4, *(const float4*)&Ar[i * 4]);
            split_store(sm, BHI_OFF, BLO_OFF, soff + i * 4, *(const float4*)&Br[i * 4]);
        }
    }
    __syncthreads();

    for (int t = 0; t < nt; t++) {
        float4 pa[4], pb[4];
        bool pf = (t + 1 < nt);
        if (pf) {
            int k0 = (t + 1) << 5;
            const float* Ar = &A[(size_t)(bm + lrow) * K + k0 + lhalf * 16];
            const float* Br = &Bt[(size_t)(bn + lrow) * K + k0 + lhalf * 16];
#pragma unroll
            for (int i = 0; i < 4; i++) {
                pa[i] = *(const float4*)&Ar[i * 4];
                pb[i] = *(const float4*)&Br[i * 4];
            }
        }

        uint32_t sa = sb + (uint32_t)(t & 1) * STG_B;
#pragma unroll
        for (int ks = 0; ks < 2; ks++) {
            uint32_t aoff2 = (a_off + ks * 16) * 2;
            uint32_t boff2 = (b_off + ks * 16) * 2;
            uint32_t ah[4][4], al[4][4], bh[4][2], bl[4][2];
#pragma unroll
            for (int mi = 0; mi < 4; mi++)
                LDSM4(ah[mi], sa + AHI_OFF + aoff2 + mi * (16 * KSTRIDE * 2));
#pragma unroll
            for (int ni = 0; ni < 4; ni++)
                LDSM2(bh[ni], sa + BHI_OFF + boff2 + ni * (8 * KSTRIDE * 2));
#pragma unroll
            for (int mi = 0; mi < 4; mi++)
#pragma unroll
                for (int ni = 0; ni < 4; ni++) MMA(acc[mi][ni], ah[mi], bh[ni]);
#pragma unroll
            for (int ni = 0; ni < 4; ni++)
                LDSM2(bl[ni], sa + BLO_OFF + boff2 + ni * (8 * KSTRIDE * 2));
#pragma unroll
            for (int mi = 0; mi < 4; mi++)
#pragma unroll
                for (int ni = 0; ni < 4; ni++) MMA(acc[mi][ni], ah[mi], bl[ni]);
#pragma unroll
            for (int mi = 0; mi < 4; mi++)
                LDSM4(al[mi], sa + ALO_OFF + aoff2 + mi * (16 * KSTRIDE * 2));
#pragma unroll
            for (int mi = 0; mi < 4; mi++)
#pragma unroll
                for (int ni = 0; ni < 4; ni++) MMA(acc[mi][ni], al[mi], bh[ni]);
        }

        if (pf) {
            char* smn = sm + ((t + 1) & 1) * STG_B;
#pragma unroll
            for (int i = 0; i < 4; i++) {
                split_store(smn, AHI_OFF, ALO_OFF, soff + i * 4, pa[i]);
                split_store(smn, BHI_OFF, BLO_OFF, soff + i * 4, pb[i]);
            }
        }
        __syncthreads();
    }

    // epilogue: direct stores (8B per lane, full 32B sectors per 4 lanes)
    int gid = lane >> 2, tig = lane & 3;
#pragma unroll
    for (int mi = 0; mi < 4; mi++) {
        int r0 = bm + warp_m + mi * 16 + gid;
#pragma unroll
        for (int ni = 0; ni < 4; ni++) {
            int cg = bn + warp_n + ni * 8 + tig * 2;
            float c0 = acc[mi][ni][0], c1 = acc[mi][ni][1];
            float c2 = acc[mi][ni][2], c3 = acc[mi][ni][3];
            if (bias) {
                float bx = bias[cg], by = bias[cg + 1];
                c0 += bx; c1 += by; c2 += bx; c3 += by;
            }
            if (relu) {
                c0 = fmaxf(c0, 0.0f); c1 = fmaxf(c1, 0.0f);
                c2 = fmaxf(c2, 0.0f); c3 = fmaxf(c3, 0.0f);
            }
            *(float2*)&C[(size_t)r0 * N + cg] = make_float2(c0, c1);
            *(float2*)&C[(size_t)(r0 + 8) * N + cg] = make_float2(c2, c3);
        }
    }
}

// ---------------- embedding + sinusoidal PE ----------------
__global__ void embed_kernel(const int* __restrict__ tokens,
                             const float* __restrict__ emb,
                             float* __restrict__ x) {
    int i = blockIdx.x * blockDim.x + threadIdx.x;
    if (i >= M_ * D_) return;
    int m = i / D_, d = i % D_;
    int s = m % S_;
    int tok = tokens[m];
    float expo = (float)(d & ~1) * (-logf(10000.0f) / (float)D_);
    float div = expf(expo);
    float ang = (float)s * div;
    float pe = (d & 1) ? cosf(ang) : sinf(ang);
    x[i] = emb[tok * D_ + d] + pe;
}

// ---------------- repack QKV weights [H][D][HD] -> [3D][D] ----------------
__global__ void repack_qkvT(const float* __restrict__ Wq,
                            const float* __restrict__ Wk,
                            const float* __restrict__ Wv,
                            float* __restrict__ wT) {
    int i = blockIdx.x * blockDim.x + threadIdx.x;
    if (i >= D_ * D_) return;
    int n = i / D_, d = i % D_;
    int h = n / HD_, e = n % HD_;
    int src = h * D_ * HD_ + d * HD_ + e;
    wT[(size_t)n * D_ + d]            = Wq[src];
    wT[(size_t)(D_ + n) * D_ + d]     = Wk[src];
    wT[(size_t)(2 * D_ + n) * D_ + d] = Wv[src];
}

// ---------------- transpose: out[C][R] = in[R][C] ----------------
__global__ void transpose_k(const float* __restrict__ in, float* __restrict__ out,
                            int R, int C) {
    __shared__ float tile[32][33];
    int c0 = blockIdx.x * 32, r0 = blockIdx.y * 32;
    int x = threadIdx.x, y = threadIdx.y;
#pragma unroll
    for (int i = 0; i < 32; i += 8)
        tile[y + i][x] = in[(size_t)(r0 + y + i) * C + c0 + x];
    __syncthreads();
#pragma unroll
    for (int i = 0; i < 32; i += 8)
        out[(size_t)(c0 + y + i) * R + r0 + x] = tile[x][y + i];
}

// ---------------- causal flash attention (fp32, thread-per-query) ----------------
__global__ __launch_bounds__(128)
void attn_kernel(const float* __restrict__ qkv, float* __restrict__ o) {
    __shared__ float Ks[64][64];
    __shared__ float Vs[64][64];
    int bh = blockIdx.y;
    int b = bh / H_, h = bh % H_;
    int sq = blockIdx.x * 128 + threadIdx.x;
    int row = b * S_ + sq;

    const float* q = qkv;
    const float* k = qkv + D_;
    const float* v = qkv + 2 * D_;

    float qr[64];
#pragma unroll
    for (int d = 0; d < 64; d++) qr[d] = q[(size_t)row * QKV_ + h * HD_ + d];

    float mx = -1e30f, l = 0.0f;
    float acc[64];
#pragma unroll
    for (int d = 0; d < 64; d++) acc[d] = 0.0f;

    const float scale = 0.125f;
    int ntiles = blockIdx.x * 2 + 2;

    for (int t = 0; t < ntiles; t++) {
        for (int i = threadIdx.x; i < 64 * 16; i += 128) {
            int j = i >> 4, d4 = (i & 15) * 4;
            size_t krow = (size_t)(b * S_ + t * 64 + j) * QKV_ + h * HD_ + d4;
            *(float4*)&Ks[j][d4] = *(const float4*)&k[krow];
            *(float4*)&Vs[j][d4] = *(const float4*)&v[krow];
        }
        __syncthreads();
        int jmax = sq - t * 64 + 1;
        if (jmax > 64) jmax = 64;
        for (int j = 0; j < jmax; j++) {
            float s = 0.0f;
            const float4* kp = (const float4*)&Ks[j][0];
#pragma unroll
            for (int d4 = 0; d4 < 16; d4++) {
                float4 kv = kp[d4];
                s += qr[d4 * 4 + 0] * kv.x + qr[d4 * 4 + 1] * kv.y +
                     qr[d4 * 4 + 2] * kv.z + qr[d4 * 4 + 3] * kv.w;
            }
            s *= scale;
            float mnew = fmaxf(mx, s);
            float corr = __expf(mx - mnew);
            float p = __expf(s - mnew);
            l = l * corr + p;
            const float4* vp = (const float4*)&Vs[j][0];
#pragma unroll
            for (int d4 = 0; d4 < 16; d4++) {
                float4 vv = vp[d4];
                acc[d4 * 4 + 0] = acc[d4 * 4 + 0] * corr + p * vv.x;
                acc[d4 * 4 + 1] = acc[d4 * 4 + 1] * corr + p * vv.y;
                acc[d4 * 4 + 2] = acc[d4 * 4 + 2] * corr + p * vv.z;
                acc[d4 * 4 + 3] = acc[d4 * 4 + 3] * corr + p * vv.w;
            }
            mx = mnew;
        }
        __syncthreads();
    }
    float inv = 1.0f / l;
#pragma unroll
    for (int d = 0; d < 64; d++)
        o[(size_t)row * D_ + h * HD_ + d] = acc[d] * inv;
}

// ---------------- residual + LayerNorm ----------------
__global__ __launch_bounds__(128)
void ln_kernel(float* __restrict__ x, const float* __restrict__ delta,
               const float* __restrict__ gamma, const float* __restrict__ beta) {
    int row = blockIdx.x;
    int tid = threadIdx.x;
    __shared__ float red[128];

    float v[4];
    float s = 0.0f;
#pragma unroll
    for (int i = 0; i < 4; i++) {
        int d = i * 128 + tid;
        float t = x[(size_t)row * D_ + d];
        if (delta) t += delta[(size_t)row * D_ + d];
        v[i] = t;
        s += t;
    }
    red[tid] = s;
    __syncthreads();
    for (int off = 64; off > 0; off >>= 1) {
        if (tid < off) red[tid] += red[tid + off];
        __syncthreads();
    }
    float mean = red[0] * (1.0f / D_);
    __syncthreads();

    float s2 = 0.0f;
#pragma unroll
    for (int i = 0; i < 4; i++) {
        float dv = v[i] - mean;
        s2 += dv * dv;
    }
    red[tid] = s2;
    __syncthreads();
    for (int off = 64; off > 0; off >>= 1) {
        if (tid < off) red[tid] += red[tid + off];
        __syncthreads();
    }
    float var = red[0] * (1.0f / D_);
    float rstd = rsqrtf(var + 1e-5f);
#pragma unroll
    for (int i = 0; i < 4; i++) {
        int d = i * 128 + tid;
        x[(size_t)row * D_ + d] = (v[i] - mean) * rstd * gamma[d] + beta[d];
    }
}

// ---------------- launch ----------------
extern "C" void kernel_launch(void* const* d_in, const int* in_sizes, int n_in,
                              void* d_out, int out_size) {
    const int* tokens    = (const int*)d_in[0];
    const float* emb     = (const float*)d_in[1];
    const float* Wq      = (const float*)d_in[2];
    const float* Wk      = (const float*)d_in[3];
    const float* Wv      = (const float*)d_in[4];
    const float* Wo      = (const float*)d_in[5];
    const float* bo      = (const float*)d_in[6];
    const float* ln1_g   = (const float*)d_in[7];
    const float* ln1_b   = (const float*)d_in[8];
    const float* W1      = (const float*)d_in[9];
    const float* b1      = (const float*)d_in[10];
    const float* W2      = (const float*)d_in[11];
    const float* b2      = (const float*)d_in[12];
    const float* ln2_g   = (const float*)d_in[13];
    const float* ln2_b   = (const float*)d_in[14];
    const float* lnf_g   = (const float*)d_in[15];
    const float* lnf_b   = (const float*)d_in[16];
    const float* head_W  = (const float*)d_in[17];
    float* out = (float*)d_out;

    float *x, *qkv, *o, *h, *wT, *woT, *w1T, *w2T;
    cudaGetSymbolAddress((void**)&x, g_x);
    cudaGetSymbolAddress((void**)&qkv, g_qkv);
    cudaGetSymbolAddress((void**)&o, g_o);
    cudaGetSymbolAddress((void**)&h, g_h);
    cudaGetSymbolAddress((void**)&wT, g_wT);
    cudaGetSymbolAddress((void**)&woT, g_woT);
    cudaGetSymbolAddress((void**)&w1T, g_w1T);
    cudaGetSymbolAddress((void**)&w2T, g_w2T);

    cudaFuncSetAttribute(gemm_tc, cudaFuncAttributeMaxDynamicSharedMemorySize, SMEM_GEMM);

    embed_kernel<<<(M_ * D_ + 255) / 256, 256>>>(tokens, emb, x);

    dim3 gQKV(QKV_ / 128, M_ / 128);
    dim3 gD(D_ / 128, M_ / 128);
    dim3 gF(F_ / 128, M_ / 128);
    dim3 gV(V_ / 128, M_ / 128);
    dim3 gAttn(S_ / 128, B_ * H_);
    dim3 tb(32, 8);

    for (int l = 0; l < L_; l++) {
        const float* Wq_l = Wq + (size_t)l * H_ * D_ * HD_;
        const float* Wk_l = Wk + (size_t)l * H_ * D_ * HD_;
        const float* Wv_l = Wv + (size_t)l * H_ * D_ * HD_;
        const float* Wo_l = Wo + (size_t)l * D_ * D_;
        const float* bo_l = bo + (size_t)l * D_;
        const float* W1_l = W1 + (size_t)l * D_ * F_;
        const float* b1_l = b1 + (size_t)l * F_;
        const float* W2_l = W2 + (size_t)l * F_ * D_;
        const float* b2_l = b2 + (size_t)l * D_;

        repack_qkvT<<<(D_ * D_ + 255) / 256, 256>>>(Wq_l, Wk_l, Wv_l, wT);
        transpose_k<<<dim3(D_ / 32, D_ / 32), tb>>>(Wo_l, woT, D_, D_);
        transpose_k<<<dim3(F_ / 32, D_ / 32), tb>>>(W1_l, w1T, D_, F_);
        transpose_k<<<dim3(D_ / 32, F_ / 32), tb>>>(W2_l, w2T, F_, D_);

        gemm_tc<<<gQKV, 256, SMEM_GEMM>>>(x, wT, nullptr, qkv, M_, QKV_, D_, 0);

        attn_kernel<<<gAttn, 128>>>(qkv, o);

        gemm_tc<<<gD, 256, SMEM_GEMM>>>(o, woT, bo_l, h, M_, D_, D_, 0);
        ln_kernel<<<M_, 128>>>(x, h, ln1_g + (size_t)l * D_, ln1_b + (size_t)l * D_);

        gemm_tc<<<gF, 256, SMEM_GEMM>>>(x, w1T, b1_l, h, M_, F_, D_, 1);
        gemm_tc<<<gD, 256, SMEM_GEMM>>>(h, w2T, b2_l, o, M_, D_, F_, 0);
        ln_kernel<<<M_, 128>>>(x, o, ln2_g + (size_t)l * D_, ln2_b + (size_t)l * D_);
    }

    ln_kernel<<<M_, 128>>>(x, nullptr, lnf_g, lnf_b);
    gemm_tc<<<gV, 256, SMEM_GEMM>>>(x, head_W, nullptr, out, M_, V_, D_, 0);
}

// round 7
// speedup vs baseline: 1.7207x; 1.0026x over previous
#include <cuda_runtime.h>
#include <cuda_bf16.h>
#include <math.h>
#include <stdint.h>

#define L_ 4
#define H_ 8
#define D_ 512
#define HD_ 64
#define F_ 2048
#define V_ 32000
#define B_ 2
#define S_ 2048
#define M_ (B_ * S_)
#define QKV_ (3 * D_)

typedef unsigned short u16;

// ---------------- scratch ----------------
__device__ float g_x[M_ * D_];
__device__ float g_qkv[M_ * QKV_];
__device__ float g_t[M_ * D_];           // proj out / ffn2 out (fp32)
__device__ u16 g_xhi[M_ * D_], g_xlo[M_ * D_];
__device__ u16 g_ohi[M_ * D_], g_olo[M_ * D_];
__device__ u16 g_hhi[M_ * F_], g_hlo[M_ * F_];
__device__ u16 g_wqh[QKV_ * D_], g_wql[QKV_ * D_];
__device__ u16 g_woh[D_ * D_],  g_wol[D_ * D_];
__device__ u16 g_w1h[F_ * D_],  g_w1l[F_ * D_];
__device__ u16 g_w2h[D_ * F_],  g_w2l[D_ * F_];
__device__ u16 g_hwh[V_ * D_],  g_hwl[V_ * D_];

// ---------------- split helpers ----------------
__device__ __forceinline__ u16 bf_hi(float v) {
    return (u16)(__float_as_uint(v) >> 16);
}
__device__ __forceinline__ u16 bf_lo(float v) {
    float hi = __uint_as_float(__float_as_uint(v) & 0xFFFF0000u);
    __nv_bfloat16 l = __float2bfloat16_rn(v - hi);
    return *(u16*)&l;
}

__device__ __forceinline__ uint32_t smem_u32(const void* p) {
    uint32_t a;
    asm("{ .reg .u64 t; cvta.to.shared.u64 t, %1; cvt.u32.u64 %0, t; }"
        : "=r"(a) : "l"(p));
    return a;
}

// ==================== bf16 mma.sync GEMM (pre-split operands) ====================
// C[M,N] = (Ahi+Alo)[M,K] @ (Bhi+Blo)[N,K]^T, 3 passes, fp32 accum.
// 128x128 CTA tile, 8 warps of 64x32, K-chunk 32, cp.async 4-stage pipeline.
#define KSTRIDE 40
#define MAT_B  (128 * KSTRIDE * 2)     // 10240 B
#define AH_OFF 0
#define AL_OFF (1 * MAT_B)
#define BH_OFF (2 * MAT_B)
#define BL_OFF (3 * MAT_B)
#define STG_B  (4 * MAT_B)             // 40960 B per stage
#define NSTG   4
#define SMEM_GEMM (NSTG * STG_B)       // 163840 B

#define CP16(s, g)  asm volatile("cp.async.cg.shared.global [%0], [%1], 16;" :: "r"(s), "l"(g))
#define CP_COMMIT() asm volatile("cp.async.commit_group;" ::: "memory")
#define CP_WAIT2()  asm volatile("cp.async.wait_group 2;" ::: "memory")

#define LDSM4(r, addr)                                                          \
    asm volatile("ldmatrix.sync.aligned.m8n8.x4.shared.b16 {%0,%1,%2,%3}, [%4];" \
                 : "=r"((r)[0]), "=r"((r)[1]), "=r"((r)[2]), "=r"((r)[3])        \
                 : "r"(addr))
#define LDSM2(r, addr)                                                          \
    asm volatile("ldmatrix.sync.aligned.m8n8.x2.shared.b16 {%0,%1}, [%2];"       \
                 : "=r"((r)[0]), "=r"((r)[1]) : "r"(addr))
#define MMA(c, a, b)                                                            \
    asm volatile("mma.sync.aligned.m16n8k16.row.col.f32.bf16.bf16.f32 "          \
                 "{%0,%1,%2,%3}, {%4,%5,%6,%7}, {%8,%9}, {%0,%1,%2,%3};"         \
                 : "+f"((c)[0]), "+f"((c)[1]), "+f"((c)[2]), "+f"((c)[3])        \
                 : "r"((a)[0]), "r"((a)[1]), "r"((a)[2]), "r"((a)[3]),           \
                   "r"((b)[0]), "r"((b)[1]))

template <bool SPLIT_OUT>
__global__ __launch_bounds__(256)
void gemm_bf16(const u16* __restrict__ Ahi, const u16* __restrict__ Alo,
               const u16* __restrict__ Bhi, const u16* __restrict__ Blo,
               const float* __restrict__ bias, float* __restrict__ Cf,
               u16* __restrict__ Chi, u16* __restrict__ Clo,
               int M, int N, int K, int relu) {
    extern __shared__ char sm[];
    uint32_t sb = smem_u32(sm);
    int tid = threadIdx.x, wid = tid >> 5, lane = tid & 31;
    int bm = blockIdx.y * 128, bn = blockIdx.x * 128;
    int warp_m = (wid & 1) * 64, warp_n = (wid >> 1) * 32;

    uint32_t a_off = (uint32_t)(warp_m + (lane & 15)) * KSTRIDE + ((lane >> 4) << 3);
    uint32_t b_off = (uint32_t)(warp_n + (lane & 7)) * KSTRIDE + (((lane >> 3) & 1) << 3);

    // cp.async mapping: 2 chunks of 16B per matrix per thread
    int c0i = tid * 2;
    int lrow0 = c0i >> 2, lc0 = (c0i & 3);        // chunk 0: row, col16
    int lrow1 = (c0i + 1) >> 2, lc1 = ((c0i + 1) & 3);

    float acc[4][4][4];
#pragma unroll
    for (int mi = 0; mi < 4; mi++)
#pragma unroll
        for (int ni = 0; ni < 4; ni++)
#pragma unroll
            for (int f = 0; f < 4; f++) acc[mi][ni][f] = 0.0f;

    int nt = K >> 5;

    // stage loader
    auto load_stage = [&](int stg, int t) {
        uint32_t ss = sb + (uint32_t)stg * STG_B;
        int k0 = t << 5;
        uint32_t s0 = lrow0 * (KSTRIDE * 2) + lc0 * 16;
        uint32_t s1 = lrow1 * (KSTRIDE * 2) + lc1 * 16;
        size_t ga0 = (size_t)(bm + lrow0) * K + k0 + lc0 * 8;
        size_t ga1 = (size_t)(bm + lrow1) * K + k0 + lc1 * 8;
        size_t gb0 = (size_t)(bn + lrow0) * K + k0 + lc0 * 8;
        size_t gb1 = (size_t)(bn + lrow1) * K + k0 + lc1 * 8;
        CP16(ss + AH_OFF + s0, &Ahi[ga0]);
        CP16(ss + AH_OFF + s1, &Ahi[ga1]);
        CP16(ss + AL_OFF + s0, &Alo[ga0]);
        CP16(ss + AL_OFF + s1, &Alo[ga1]);
        CP16(ss + BH_OFF + s0, &Bhi[gb0]);
        CP16(ss + BH_OFF + s1, &Bhi[gb1]);
        CP16(ss + BL_OFF + s0, &Blo[gb0]);
        CP16(ss + BL_OFF + s1, &Blo[gb1]);
    };

    // prologue: stages 0..2
#pragma unroll
    for (int s = 0; s < NSTG - 1; s++) {
        if (s < nt) load_stage(s, s);
        CP_COMMIT();
    }

    for (int t = 0; t < nt; t++) {
        CP_WAIT2();
        __syncthreads();

        uint32_t sa = sb + (uint32_t)(t & (NSTG - 1)) * STG_B;
#pragma unroll
        for (int ks = 0; ks < 2; ks++) {
            uint32_t aoff2 = (a_off + ks * 16) * 2;
            uint32_t boff2 = (b_off + ks * 16) * 2;
            uint32_t ah[4][4], al[4][4], bh[4][2], bl[4][2];
#pragma unroll
            for (int mi = 0; mi < 4; mi++)
                LDSM4(ah[mi], sa + AH_OFF + aoff2 + mi * (16 * KSTRIDE * 2));
#pragma unroll
            for (int ni = 0; ni < 4; ni++)
                LDSM2(bh[ni], sa + BH_OFF + boff2 + ni * (8 * KSTRIDE * 2));
#pragma unroll
            for (int mi = 0; mi < 4; mi++)
#pragma unroll
                for (int ni = 0; ni < 4; ni++) MMA(acc[mi][ni], ah[mi], bh[ni]);
#pragma unroll
            for (int ni = 0; ni < 4; ni++)
                LDSM2(bl[ni], sa + BL_OFF + boff2 + ni * (8 * KSTRIDE * 2));
#pragma unroll
            for (int mi = 0; mi < 4; mi++)
#pragma unroll
                for (int ni = 0; ni < 4; ni++) MMA(acc[mi][ni], ah[mi], bl[ni]);
#pragma unroll
            for (int mi = 0; mi < 4; mi++)
                LDSM4(al[mi], sa + AL_OFF + aoff2 + mi * (16 * KSTRIDE * 2));
#pragma unroll
            for (int mi = 0; mi < 4; mi++)
#pragma unroll
                for (int ni = 0; ni < 4; ni++) MMA(acc[mi][ni], al[mi], bh[ni]);
        }

        if (t + NSTG - 1 < nt) load_stage((t + NSTG - 1) & (NSTG - 1), t + NSTG - 1);
        CP_COMMIT();
    }

    // epilogue
    int gid = lane >> 2, tig = lane & 3;
#pragma unroll
    for (int mi = 0; mi < 4; mi++) {
        int r0 = bm + warp_m + mi * 16 + gid;
#pragma unroll
        for (int ni = 0; ni < 4; ni++) {
            int cg = bn + warp_n + ni * 8 + tig * 2;
            float c0 = acc[mi][ni][0], c1 = acc[mi][ni][1];
            float c2 = acc[mi][ni][2], c3 = acc[mi][ni][3];
            if (bias) {
                float bx = bias[cg], by = bias[cg + 1];
                c0 += bx; c1 += by; c2 += bx; c3 += by;
            }
            if (relu) {
                c0 = fmaxf(c0, 0.0f); c1 = fmaxf(c1, 0.0f);
                c2 = fmaxf(c2, 0.0f); c3 = fmaxf(c3, 0.0f);
            }
            if (SPLIT_OUT) {
                size_t i0 = (size_t)r0 * N + cg, i1 = (size_t)(r0 + 8) * N + cg;
                *(uint32_t*)&Chi[i0] = (uint32_t)bf_hi(c0) | ((uint32_t)bf_hi(c1) << 16);
                *(uint32_t*)&Clo[i0] = (uint32_t)bf_lo(c0) | ((uint32_t)bf_lo(c1) << 16);
                *(uint32_t*)&Chi[i1] = (uint32_t)bf_hi(c2) | ((uint32_t)bf_hi(c3) << 16);
                *(uint32_t*)&Clo[i1] = (uint32_t)bf_lo(c2) | ((uint32_t)bf_lo(c3) << 16);
            } else {
                *(float2*)&Cf[(size_t)r0 * N + cg] = make_float2(c0, c1);
                *(float2*)&Cf[(size_t)(r0 + 8) * N + cg] = make_float2(c2, c3);
            }
        }
    }
}

// ---------------- embedding + PE (+ split) ----------------
__global__ void embed_kernel(const int* __restrict__ tokens,
                             const float* __restrict__ emb,
                             float* __restrict__ x,
                             u16* __restrict__ xhi, u16* __restrict__ xlo) {
    int i = blockIdx.x * blockDim.x + threadIdx.x;
    if (i >= M_ * D_) return;
    int m = i / D_, d = i % D_;
    int s = m % S_;
    int tok = tokens[m];
    float expo = (float)(d & ~1) * (-logf(10000.0f) / (float)D_);
    float ang = (float)s * expf(expo);
    float pe = (d & 1) ? cosf(ang) : sinf(ang);
    float v = emb[tok * D_ + d] + pe;
    x[i] = v;
    xhi[i] = bf_hi(v);
    xlo[i] = bf_lo(v);
}

// ---------------- repack QKV weights -> [3D][D] split ----------------
__global__ void repack_qkvT_split(const float* __restrict__ Wq,
                                  const float* __restrict__ Wk,
                                  const float* __restrict__ Wv,
                                  u16* __restrict__ whi, u16* __restrict__ wlo) {
    int i = blockIdx.x * blockDim.x + threadIdx.x;
    if (i >= D_ * D_) return;
    int n = i / D_, d = i % D_;
    int h = n / HD_, e = n % HD_;
    int src = h * D_ * HD_ + d * HD_ + e;
    float vq = Wq[src], vk = Wk[src], vv = Wv[src];
    size_t iq = (size_t)n * D_ + d;
    whi[iq] = bf_hi(vq); wlo[iq] = bf_lo(vq);
    whi[iq + (size_t)D_ * D_] = bf_hi(vk); wlo[iq + (size_t)D_ * D_] = bf_lo(vk);
    whi[iq + (size_t)2 * D_ * D_] = bf_hi(vv); wlo[iq + (size_t)2 * D_ * D_] = bf_lo(vv);
}

// ---------------- transpose + split: out[C][R] = split(in[R][C]) ----------------
__global__ void transpose_split(const float* __restrict__ in,
                                u16* __restrict__ ohi, u16* __restrict__ olo,
                                int R, int C) {
    __shared__ float tile[32][33];
    int c0 = blockIdx.x * 32, r0 = blockIdx.y * 32;
    int x = threadIdx.x, y = threadIdx.y;
#pragma unroll
    for (int i = 0; i < 32; i += 8)
        tile[y + i][x] = in[(size_t)(r0 + y + i) * C + c0 + x];
    __syncthreads();
#pragma unroll
    for (int i = 0; i < 32; i += 8) {
        float v = tile[x][y + i];
        size_t idx = (size_t)(c0 + y + i) * R + r0 + x;
        ohi[idx] = bf_hi(v);
        olo[idx] = bf_lo(v);
    }
}

// ---------------- plain split (head_W) ----------------
__global__ void split_plain(const float* __restrict__ in,
                            u16* __restrict__ ohi, u16* __restrict__ olo, int n) {
    int i = blockIdx.x * blockDim.x + threadIdx.x;
    if (i >= n) return;
    float v = in[i];
    ohi[i] = bf_hi(v);
    olo[i] = bf_lo(v);
}

// ---------------- causal flash attention (fp32), writes split output ----------------
__global__ __launch_bounds__(128)
void attn_kernel(const float* __restrict__ qkv,
                 u16* __restrict__ ohi, u16* __restrict__ olo) {
    __shared__ float Ks[64][64];
    __shared__ float Vs[64][64];
    int bh = blockIdx.y;
    int b = bh / H_, h = bh % H_;
    int sq = blockIdx.x * 128 + threadIdx.x;
    int row = b * S_ + sq;

    const float* q = qkv;
    const float* k = qkv + D_;
    const float* v = qkv + 2 * D_;

    float qr[64];
#pragma unroll
    for (int d = 0; d < 64; d++) qr[d] = q[(size_t)row * QKV_ + h * HD_ + d];

    float mx = -1e30f, l = 0.0f;
    float acc[64];
#pragma unroll
    for (int d = 0; d < 64; d++) acc[d] = 0.0f;

    const float scale = 0.125f;
    int ntiles = blockIdx.x * 2 + 2;

    for (int t = 0; t < ntiles; t++) {
        for (int i = threadIdx.x; i < 64 * 16; i += 128) {
            int j = i >> 4, d4 = (i & 15) * 4;
            size_t krow = (size_t)(b * S_ + t * 64 + j) * QKV_ + h * HD_ + d4;
            *(float4*)&Ks[j][d4] = *(const float4*)&k[krow];
            *(float4*)&Vs[j][d4] = *(const float4*)&v[krow];
        }
        __syncthreads();
        int jmax = sq - t * 64 + 1;
        if (jmax > 64) jmax = 64;
        for (int j = 0; j < jmax; j++) {
            float s = 0.0f;
            const float4* kp = (const float4*)&Ks[j][0];
#pragma unroll
            for (int d4 = 0; d4 < 16; d4++) {
                float4 kv = kp[d4];
                s += qr[d4 * 4 + 0] * kv.x + qr[d4 * 4 + 1] * kv.y +
                     qr[d4 * 4 + 2] * kv.z + qr[d4 * 4 + 3] * kv.w;
            }
            s *= scale;
            float mnew = fmaxf(mx, s);
            float corr = __expf(mx - mnew);
            float p = __expf(s - mnew);
            l = l * corr + p;
            const float4* vp = (const float4*)&Vs[j][0];
#pragma unroll
            for (int d4 = 0; d4 < 16; d4++) {
                float4 vv = vp[d4];
                acc[d4 * 4 + 0] = acc[d4 * 4 + 0] * corr + p * vv.x;
                acc[d4 * 4 + 1] = acc[d4 * 4 + 1] * corr + p * vv.y;
                acc[d4 * 4 + 2] = acc[d4 * 4 + 2] * corr + p * vv.z;
                acc[d4 * 4 + 3] = acc[d4 * 4 + 3] * corr + p * vv.w;
            }
            mx = mnew;
        }
        __syncthreads();
    }
    float inv = 1.0f / l;
#pragma unroll
    for (int d = 0; d < 64; d++) {
        float val = acc[d] * inv;
        size_t idx = (size_t)row * D_ + h * HD_ + d;
        ohi[idx] = bf_hi(val);
        olo[idx] = bf_lo(val);
    }
}

// ---------------- residual + LayerNorm (+ split) ----------------
__global__ __launch_bounds__(128)
void ln_kernel(float* __restrict__ x, const float* __restrict__ delta,
               const float* __restrict__ gamma, const float* __restrict__ beta,
               u16* __restrict__ xhi, u16* __restrict__ xlo) {
    int row = blockIdx.x;
    int tid = threadIdx.x;
    __shared__ float red[128];

    float v[4];
    float s = 0.0f;
#pragma unroll
    for (int i = 0; i < 4; i++) {
        int d = i * 128 + tid;
        float t = x[(size_t)row * D_ + d];
        if (delta) t += delta[(size_t)row * D_ + d];
        v[i] = t;
        s += t;
    }
    red[tid] = s;
    __syncthreads();
    for (int off = 64; off > 0; off >>= 1) {
        if (tid < off) red[tid] += red[tid + off];
        __syncthreads();
    }
    float mean = red[0] * (1.0f / D_);
    __syncthreads();

    float s2 = 0.0f;
#pragma unroll
    for (int i = 0; i < 4; i++) {
        float dv = v[i] - mean;
        s2 += dv * dv;
    }
    red[tid] = s2;
    __syncthreads();
    for (int off = 64; off > 0; off >>= 1) {
        if (tid < off) red[tid] += red[tid + off];
        __syncthreads();
    }
    float var = red[0] * (1.0f / D_);
    float rstd = rsqrtf(var + 1e-5f);
#pragma unroll
    for (int i = 0; i < 4; i++) {
        int d = i * 128 + tid;
        float o = (v[i] - mean) * rstd * gamma[d] + beta[d];
        size_t idx = (size_t)row * D_ + d;
        x[idx] = o;
        xhi[idx] = bf_hi(o);
        xlo[idx] = bf_lo(o);
    }
}

// ---------------- launch ----------------
extern "C" void kernel_launch(void* const* d_in, const int* in_sizes, int n_in,
                              void* d_out, int out_size) {
    const int* tokens    = (const int*)d_in[0];
    const float* emb     = (const float*)d_in[1];
    const float* Wq      = (const float*)d_in[2];
    const float* Wk      = (const float*)d_in[3];
    const float* Wv      = (const float*)d_in[4];
    const float* Wo      = (const float*)d_in[5];
    const float* bo      = (const float*)d_in[6];
    const float* ln1_g   = (const float*)d_in[7];
    const float* ln1_b   = (const float*)d_in[8];
    const float* W1      = (const float*)d_in[9];
    const float* b1      = (const float*)d_in[10];
    const float* W2      = (const float*)d_in[11];
    const float* b2      = (const float*)d_in[12];
    const float* ln2_g   = (const float*)d_in[13];
    const float* ln2_b   = (const float*)d_in[14];
    const float* lnf_g   = (const float*)d_in[15];
    const float* lnf_b   = (const float*)d_in[16];
    const float* head_W  = (const float*)d_in[17];
    float* out = (float*)d_out;

    float *x, *qkv, *t;
    u16 *xhi, *xlo, *ohi, *olo, *hhi, *hlo;
    u16 *wqh, *wql, *woh, *wol, *w1h, *w1l, *w2h, *w2l, *hwh, *hwl;
    cudaGetSymbolAddress((void**)&x, g_x);
    cudaGetSymbolAddress((void**)&qkv, g_qkv);
    cudaGetSymbolAddress((void**)&t, g_t);
    cudaGetSymbolAddress((void**)&xhi, g_xhi);
    cudaGetSymbolAddress((void**)&xlo, g_xlo);
    cudaGetSymbolAddress((void**)&ohi, g_ohi);
    cudaGetSymbolAddress((void**)&olo, g_olo);
    cudaGetSymbolAddress((void**)&hhi, g_hhi);
    cudaGetSymbolAddress((void**)&hlo, g_hlo);
    cudaGetSymbolAddress((void**)&wqh, g_wqh);
    cudaGetSymbolAddress((void**)&wql, g_wql);
    cudaGetSymbolAddress((void**)&woh, g_woh);
    cudaGetSymbolAddress((void**)&wol, g_wol);
    cudaGetSymbolAddress((void**)&w1h, g_w1h);
    cudaGetSymbolAddress((void**)&w1l, g_w1l);
    cudaGetSymbolAddress((void**)&w2h, g_w2h);
    cudaGetSymbolAddress((void**)&w2l, g_w2l);
    cudaGetSymbolAddress((void**)&hwh, g_hwh);
    cudaGetSymbolAddress((void**)&hwl, g_hwl);

    cudaFuncSetAttribute(gemm_bf16<false>, cudaFuncAttributeMaxDynamicSharedMemorySize, SMEM_GEMM);
    cudaFuncSetAttribute(gemm_bf16<true>,  cudaFuncAttributeMaxDynamicSharedMemorySize, SMEM_GEMM);

    embed_kernel<<<(M_ * D_ + 255) / 256, 256>>>(tokens, emb, x, xhi, xlo);
    split_plain<<<(V_ * D_ + 255) / 256, 256>>>(head_W, hwh, hwl, V_ * D_);

    dim3 gQKV(QKV_ / 128, M_ / 128);
    dim3 gD(D_ / 128, M_ / 128);
    dim3 gF(F_ / 128, M_ / 128);
    dim3 gV(V_ / 128, M_ / 128);
    dim3 gAttn(S_ / 128, B_ * H_);
    dim3 tb(32, 8);

    for (int l = 0; l < L_; l++) {
        const float* Wq_l = Wq + (size_t)l * H_ * D_ * HD_;
        const float* Wk_l = Wk + (size_t)l * H_ * D_ * HD_;
        const float* Wv_l = Wv + (size_t)l * H_ * D_ * HD_;
        const float* Wo_l = Wo + (size_t)l * D_ * D_;
        const float* bo_l = bo + (size_t)l * D_;
        const float* W1_l = W1 + (size_t)l * D_ * F_;
        const float* b1_l = b1 + (size_t)l * F_;
        const float* W2_l = W2 + (size_t)l * F_ * D_;
        const float* b2_l = b2 + (size_t)l * D_;

        repack_qkvT_split<<<(D_ * D_ + 255) / 256, 256>>>(Wq_l, Wk_l, Wv_l, wqh, wql);
        transpose_split<<<dim3(D_ / 32, D_ / 32), tb>>>(Wo_l, woh, wol, D_, D_);
        transpose_split<<<dim3(F_ / 32, D_ / 32), tb>>>(W1_l, w1h, w1l, D_, F_);
        transpose_split<<<dim3(D_ / 32, F_ / 32), tb>>>(W2_l, w2h, w2l, F_, D_);

        gemm_bf16<false><<<gQKV, 256, SMEM_GEMM>>>(xhi, xlo, wqh, wql, nullptr,
                                                   qkv, nullptr, nullptr, M_, QKV_, D_, 0);

        attn_kernel<<<gAttn, 128>>>(qkv, ohi, olo);

        gemm_bf16<false><<<gD, 256, SMEM_GEMM>>>(ohi, olo, woh, wol, bo_l,
                                                 t, nullptr, nullptr, M_, D_, D_, 0);
        ln_kernel<<<M_, 128>>>(x, t, ln1_g + (size_t)l * D_, ln1_b + (size_t)l * D_, xhi, xlo);

        gemm_bf16<true><<<gF, 256, SMEM_GEMM>>>(xhi, xlo, w1h, w1l, b1_l,
                                                nullptr, hhi, hlo, M_, F_, D_, 1);
        gemm_bf16<false><<<gD, 256, SMEM_GEMM>>>(hhi, hlo, w2h, w2l, b2_l,
                                                 t, nullptr, nullptr, M_, D_, F_, 0);
        ln_kernel<<<M_, 128>>>(x, t, ln2_g + (size_t)l * D_, ln2_b + (size_t)l * D_, xhi, xlo);
    }

    ln_kernel<<<M_, 128>>>(x, nullptr, lnf_g, lnf_b, xhi, xlo);
    gemm_bf16<false><<<gV, 256, SMEM_GEMM>>>(xhi, xlo, hwh, hwl, nullptr,
                                             out, nullptr, nullptr, M_, V_, D_, 0);
}